// round 15
// baseline (speedup 1.0000x reference)
#include <cuda_runtime.h>
#include <cuda_bf16.h>
#include <cuda_fp16.h>
#include <math.h>
#include <stdint.h>

// Problem constants
#define B_SZ   8
#define T_LEN  1024
#define C_DIM  1024
#define H_NUM  16
#define D_HEAD 64
#define BH     (B_SZ * H_NUM)        // 128
#define M_ROWS (B_SZ * T_LEN)        // 8192
#define K_DIM  1024

// fp32 scratch (pre-rotary q/k only)
__device__ float g_q[BH * T_LEN * D_HEAD];
__device__ float g_k[BH * T_LEN * D_HEAD];

// 16-bit buffers (payload dtype noted; arrays typed bf16 for storage only)
__device__ __nv_bfloat16 g_xhi[M_ROWS * K_DIM];         // fp16 payload
__device__ __nv_bfloat16 g_xlo[M_ROWS * K_DIM];         // fp16 payload
__device__ __nv_bfloat16 g_wahi[3 * C_DIM * K_DIM];     // fp16 payload
__device__ __nv_bfloat16 g_walo[3 * C_DIM * K_DIM];     // fp16 payload
__device__ __nv_bfloat16 g_wph[C_DIM * K_DIM];          // fp16 payload
__device__ __nv_bfloat16 g_qhi[BH * T_LEN * D_HEAD];    // bf16
__device__ __nv_bfloat16 g_qlo[BH * T_LEN * D_HEAD];    // bf16
__device__ __nv_bfloat16 g_khi[BH * T_LEN * D_HEAD];    // bf16
__device__ __nv_bfloat16 g_klo[BH * T_LEN * D_HEAD];    // bf16
__device__ __nv_bfloat16 g_vhi[BH * T_LEN * D_HEAD];    // fp16 payload (single)
__device__ __nv_bfloat16 g_yhi[M_ROWS * C_DIM];         // fp16 payload (single)

// ---------------------------------------------------------------------------
// helpers
// ---------------------------------------------------------------------------
__device__ __forceinline__ uint32_t smem_u32(const void* p) {
    uint32_t a;
    asm("{ .reg .u64 t; cvta.to.shared.u64 t, %1; cvt.u32.u64 %0, t; }"
        : "=r"(a) : "l"(p));
    return a;
}
__device__ __forceinline__ void cp16(uint32_t dst, const void* src) {
    asm volatile("cp.async.cg.shared.global [%0], [%1], 16;" :: "r"(dst), "l"(src));
}
__device__ __forceinline__ void cp_commit() {
    asm volatile("cp.async.commit_group;" ::: "memory");
}
__device__ __forceinline__ void cp_wait1() {
    asm volatile("cp.async.wait_group 1;" ::: "memory");
}
__device__ __forceinline__ void cp_wait0() {
    asm volatile("cp.async.wait_group 0;" ::: "memory");
}
__device__ __forceinline__ void ldmat4(uint32_t* r, uint32_t addr) {
    asm volatile("ldmatrix.sync.aligned.m8n8.x4.shared.b16 {%0,%1,%2,%3}, [%4];"
                 : "=r"(r[0]), "=r"(r[1]), "=r"(r[2]), "=r"(r[3]) : "r"(addr));
}
__device__ __forceinline__ void ldmat2(uint32_t* r, uint32_t addr) {
    asm volatile("ldmatrix.sync.aligned.m8n8.x2.shared.b16 {%0,%1}, [%2];"
                 : "=r"(r[0]), "=r"(r[1]) : "r"(addr));
}
__device__ __forceinline__ void ldmat2t(uint32_t* r, uint32_t addr) {
    asm volatile("ldmatrix.sync.aligned.m8n8.x2.trans.shared.b16 {%0,%1}, [%2];"
                 : "=r"(r[0]), "=r"(r[1]) : "r"(addr));
}
// bf16 MMA (fp32 accum)
__device__ __forceinline__ void mma16816(float* c, const uint32_t* a, const uint32_t* b) {
    asm volatile(
        "mma.sync.aligned.m16n8k16.row.col.f32.bf16.bf16.f32 "
        "{%0,%1,%2,%3}, {%4,%5,%6,%7}, {%8,%9}, {%0,%1,%2,%3};"
        : "+f"(c[0]), "+f"(c[1]), "+f"(c[2]), "+f"(c[3])
        : "r"(a[0]), "r"(a[1]), "r"(a[2]), "r"(a[3]), "r"(b[0]), "r"(b[1]));
}
// fp16 MMA (fp32 accum)
__device__ __forceinline__ void mma16816h(float* c, const uint32_t* a, const uint32_t* b) {
    asm volatile(
        "mma.sync.aligned.m16n8k16.row.col.f32.f16.f16.f32 "
        "{%0,%1,%2,%3}, {%4,%5,%6,%7}, {%8,%9}, {%0,%1,%2,%3};"
        : "+f"(c[0]), "+f"(c[1]), "+f"(c[2]), "+f"(c[3])
        : "r"(a[0]), "r"(a[1]), "r"(a[2]), "r"(a[3]), "r"(b[0]), "r"(b[1]));
}
__device__ __forceinline__ uint32_t packbf(float a, float b) {
    uint32_t r;
    asm("cvt.rn.bf16x2.f32 %0, %1, %2;" : "=r"(r) : "f"(b), "f"(a));
    return r;
}
__device__ __forceinline__ uint32_t packh(float a, float b) {
    uint32_t r;
    asm("cvt.rn.f16x2.f32 %0, %1, %2;" : "=r"(r) : "f"(b), "f"(a));
    return r;
}
__device__ __forceinline__ float qmax(float x) {
    x = fmaxf(x, __shfl_xor_sync(0xffffffffu, x, 1));
    x = fmaxf(x, __shfl_xor_sync(0xffffffffu, x, 2));
    return x;
}
__device__ __forceinline__ float qsum(float x) {
    x += __shfl_xor_sync(0xffffffffu, x, 1);
    x += __shfl_xor_sync(0xffffffffu, x, 2);
    return x;
}

// ---------------------------------------------------------------------------
// fp32 -> (fp16 hi, fp16 lo) split
// ---------------------------------------------------------------------------
__global__ __launch_bounds__(256) void hsplit_kernel(const float* __restrict__ src,
                                                     __nv_bfloat16* __restrict__ hi,
                                                     __nv_bfloat16* __restrict__ lo,
                                                     int n4) {
    int i = blockIdx.x * blockDim.x + threadIdx.x;
    if (i >= n4) return;
    float4 x = ((const float4*)src)[i];
    float xs[4] = {x.x, x.y, x.z, x.w};
    float hs[4];
#pragma unroll
    for (int e = 0; e < 4; e++) hs[e] = __half2float(__float2half(xs[e]));
    uint2 ho, lv;
    ho.x = packh(xs[0], xs[1]);
    ho.y = packh(xs[2], xs[3]);
    lv.x = packh(xs[0] - hs[0], xs[1] - hs[1]);
    lv.y = packh(xs[2] - hs[2], xs[3] - hs[3]);
    ((uint2*)hi)[i] = ho;
    ((uint2*)lo)[i] = lv;
}

// fp32 -> fp16 (single) convert, for Wp
__global__ __launch_bounds__(256) void half_kernel(const float* __restrict__ src,
                                                   __nv_bfloat16* __restrict__ dst,
                                                   int n4) {
    int i = blockIdx.x * blockDim.x + threadIdx.x;
    if (i >= n4) return;
    float4 x = ((const float4*)src)[i];
    uint2 out;
    out.x = packh(x.x, x.y);
    out.y = packh(x.z, x.w);
    ((uint2*)dst)[i] = out;
}

// ---------------------------------------------------------------------------
// QKV GEMM (fp16): 256x128 tile, BK=32, 3-stage cp.async pipeline, 1 CTA/SM.
// q,k columns: 3 terms xh*Wh + xl*Wh + xh*Wl; v columns: 2 terms (xh+xl)*Wh.
// Epilogue: q,k fp32 head-layout; v -> single fp16 head-layout.
// ---------------------------------------------------------------------------
#define GSKB 80                        // bytes per 32-fp16 row
#define Q_OFF_AL (256 * GSKB)          // 20480
#define Q_OFF_BH (512 * GSKB)          // 40960
#define Q_OFF_BL (640 * GSKB)          // 51200
#define Q_STAGE  (768 * GSKB)          // 61440 per stage
#define DSMEM_Q  (3 * Q_STAGE)         // 184320 -> 1 CTA/SM

__global__ __launch_bounds__(256, 1) void gemm_qkv(
    const __nv_bfloat16* __restrict__ Ahi, const __nv_bfloat16* __restrict__ Alo,
    const __nv_bfloat16* __restrict__ Bhi, const __nv_bfloat16* __restrict__ Blo) {
    extern __shared__ char dsm[];
    const uint32_t sbase = smem_u32(dsm);

    const int tid  = threadIdx.x;
    const int lane = tid & 31;
    const int wid  = tid >> 5;
    const int wm   = (wid & 3) * 64;   // 4 m-warps
    const int wn   = (wid >> 2) * 64;  // 2 n-warps
    const int bn   = blockIdx.x * 128;
    const int bm   = blockIdx.y * 256;
    const bool qk  = (bn < 2048);

    float c[4][8][4];
#pragma unroll
    for (int mi = 0; mi < 4; mi++)
#pragma unroll
        for (int ni = 0; ni < 8; ni++)
#pragma unroll
            for (int e = 0; e < 4; e++) c[mi][ni][e] = 0.f;

    // flat loader: rows [0,256)=Ahi, [256,512)=Alo, [512,640)=Bhi, [640,768)=Blo
    auto issue = [&](int ch) {
        const int k0 = ch * 32;
        const uint32_t bb = sbase + (uint32_t)(ch % 3) * Q_STAGE;
        const int niter = qk ? 12 : 10;          // 768 or 640 rows * 4 segs / 256
        for (int it = 0; it < niter; it++) {
            const int idx = tid + it * 256;
            const int row = idx >> 2;
            const int seg = idx & 3;
            const __nv_bfloat16* src;
            int gb, r;
            if (row < 256)      { src = Ahi; gb = bm; r = row; }
            else if (row < 512) { src = Alo; gb = bm; r = row - 256; }
            else if (row < 640) { src = Bhi; gb = bn; r = row - 512; }
            else                { src = Blo; gb = bn; r = row - 640; }
            cp16(bb + (uint32_t)row * GSKB + seg * 16,
                 src + (size_t)(gb + r) * K_DIM + k0 + seg * 8);
        }
        cp_commit();
    };

    issue(0);
    issue(1);

    const int arow = lane & 15;
    const int acol = (lane >> 4) << 3;
    const int brow = lane & 7;
    const int bcol = ((lane >> 3) & 1) << 3;

    for (int ch = 0; ch < 32; ch++) {
        if (ch < 31) cp_wait1();   // chunk ch landed; ch+1 may stay in flight
        else         cp_wait0();
        __syncthreads();
        if (ch + 2 < 32) issue(ch + 2);   // buffer (ch+2)%3 == (ch-1)%3, free

        const uint32_t bb = sbase + (uint32_t)(ch % 3) * Q_STAGE;

#pragma unroll
        for (int k16 = 0; k16 < 2; k16++) {
            uint32_t bh[8][2], bl[8][2];
#pragma unroll
            for (int ni = 0; ni < 8; ni++) {
                const uint32_t bd = bb + Q_OFF_BH
                                  + (uint32_t)(wn + ni * 8 + brow) * GSKB
                                  + (uint32_t)(k16 * 16 + bcol) * 2;
                ldmat2(bh[ni], bd);
                if (qk) ldmat2(bl[ni], bd + (Q_OFF_BL - Q_OFF_BH));
            }
#pragma unroll
            for (int mi = 0; mi < 4; mi++) {
                uint32_t ah[4], al[4];
                const uint32_t ad = bb + (uint32_t)(wm + mi * 16 + arow) * GSKB
                                  + (uint32_t)(k16 * 16 + acol) * 2;
                ldmat4(ah, ad);
                ldmat4(al, ad + Q_OFF_AL);
#pragma unroll
                for (int ni = 0; ni < 8; ni++) {
                    mma16816h(c[mi][ni], ah, bh[ni]);
                    mma16816h(c[mi][ni], al, bh[ni]);
                    if (qk) mma16816h(c[mi][ni], ah, bl[ni]);
                }
            }
        }
    }

    const int g  = lane >> 2;
    const int tg = lane & 3;
#pragma unroll
    for (int mi = 0; mi < 4; mi++) {
#pragma unroll
        for (int ni = 0; ni < 8; ni++) {
            const int n = bn + wn + ni * 8 + 2 * tg;
            const int m0r = bm + wm + mi * 16 + g;
            const int part = n >> 10;
            const int cc = n & 1023;
            const int h = cc >> 6;
            const int d = cc & 63;
#pragma unroll
            for (int rr = 0; rr < 2; rr++) {
                const int m = m0r + rr * 8;
                const int b = m >> 10;
                const int t = m & 1023;
                const size_t off = ((size_t)(b * 16 + h) * T_LEN + t) * D_HEAD + d;
                float2 v = rr ? make_float2(c[mi][ni][2], c[mi][ni][3])
                              : make_float2(c[mi][ni][0], c[mi][ni][1]);
                if (part == 0)      *(float2*)(g_q + off) = v;
                else if (part == 1) *(float2*)(g_k + off) = v;
                else                *(uint32_t*)(g_vhi + off) = packh(v.x, v.y);
            }
        }
    }
}

// ---------------------------------------------------------------------------
// Projection GEMM (fp16, 1 term): out = y * Wp^T  (verified R14)
// ---------------------------------------------------------------------------
#define GTILE (128 * GSKB)           // 10240
#define PBUF (2 * GTILE)             // 20480
#define DSMEM_P (2 * PBUF)           // 40960

__global__ __launch_bounds__(256, 2) void gemm_proj(
    const __nv_bfloat16* __restrict__ A, const __nv_bfloat16* __restrict__ B,
    float* __restrict__ Cout) {
    extern __shared__ char dsm[];
    const uint32_t sbase = smem_u32(dsm);

    const int tid  = threadIdx.x;
    const int lane = tid & 31;
    const int wid  = tid >> 5;
    const int wm   = (wid & 1) * 64;
    const int wn   = (wid >> 1) * 32;
    const int bn   = blockIdx.x * 128;
    const int bm   = blockIdx.y * 128;

    float c[4][4][4];
#pragma unroll
    for (int mi = 0; mi < 4; mi++)
#pragma unroll
        for (int ni = 0; ni < 4; ni++)
#pragma unroll
            for (int e = 0; e < 4; e++) c[mi][ni][e] = 0.f;

    const __nv_bfloat16* srcs[2] = {A, B};
    const int gbase[2] = {bm, bn};

    auto issue = [&](int ch, int buf) {
        const int k0 = ch * 32;
        const uint32_t bb = sbase + (uint32_t)buf * PBUF;
#pragma unroll
        for (int it = 0; it < 4; it++) {
            const int idx = tid + it * 256;
            const int t = idx >> 9;
            const int rem = idx & 511;
            const int row = rem >> 2;
            const int seg = rem & 3;
            cp16(bb + (uint32_t)t * GTILE + (uint32_t)row * GSKB + seg * 16,
                 srcs[t] + (size_t)(gbase[t] + row) * K_DIM + k0 + seg * 8);
        }
        cp_commit();
    };

    issue(0, 0);

    const int arow = lane & 15;
    const int acol = (lane >> 4) << 3;
    const int brow = lane & 7;
    const int bcol = ((lane >> 3) & 1) << 3;

    for (int ch = 0; ch < 32; ch++) {
        cp_wait0();
        __syncthreads();
        if (ch < 31) issue(ch + 1, (ch + 1) & 1);

        const uint32_t bb = sbase + (uint32_t)(ch & 1) * PBUF;
        const uint32_t abase = bb;
        const uint32_t bbase = bb + GTILE;

#pragma unroll
        for (int k16 = 0; k16 < 2; k16++) {
            uint32_t bw[4][2];
#pragma unroll
            for (int ni = 0; ni < 4; ni++) {
                const uint32_t bd = bbase + (uint32_t)(wn + ni * 8 + brow) * GSKB
                                  + (uint32_t)(k16 * 16 + bcol) * 2;
                ldmat2(bw[ni], bd);
            }
#pragma unroll
            for (int mi = 0; mi < 4; mi++) {
                uint32_t ah[4];
                const uint32_t ad = abase + (uint32_t)(wm + mi * 16 + arow) * GSKB
                                  + (uint32_t)(k16 * 16 + acol) * 2;
                ldmat4(ah, ad);
#pragma unroll
                for (int ni = 0; ni < 4; ni++)
                    mma16816h(c[mi][ni], ah, bw[ni]);
            }
        }
    }

    const int g  = lane >> 2;
    const int tg = lane & 3;
#pragma unroll
    for (int mi = 0; mi < 4; mi++) {
#pragma unroll
        for (int ni = 0; ni < 4; ni++) {
            const int n = bn + wn + ni * 8 + 2 * tg;
            const int m0r = bm + wm + mi * 16 + g;
            *(float2*)(Cout + (size_t)m0r * C_DIM + n) =
                make_float2(c[mi][ni][0], c[mi][ni][1]);
            *(float2*)(Cout + (size_t)(m0r + 8) * C_DIM + n) =
                make_float2(c[mi][ni][2], c[mi][ni][3]);
        }
    }
}

// ---------------------------------------------------------------------------
// Rotary: fast __sincosf; outputs bf16 hi/lo of rotated q,k (verified)
// ---------------------------------------------------------------------------
__global__ __launch_bounds__(256) void rotary_kernel() {
    const int idx = blockIdx.x * blockDim.x + threadIdx.x;
    if (idx >= BH * T_LEN) return;
    const float* qp = g_q + (size_t)idx * D_HEAD;
    const float* kp = g_k + (size_t)idx * D_HEAD;

    float q[64], k[64];
#pragma unroll
    for (int i = 0; i < 16; i++) {
        ((float4*)q)[i] = ((const float4*)qp)[i];
        ((float4*)k)[i] = ((const float4*)kp)[i];
    }
    uint32_t* qh32 = (uint32_t*)g_qhi + (size_t)idx * 32;
    uint32_t* ql32 = (uint32_t*)g_qlo + (size_t)idx * 32;
    uint32_t* kh32 = (uint32_t*)g_khi + (size_t)idx * 32;
    uint32_t* kl32 = (uint32_t*)g_klo + (size_t)idx * 32;

#pragma unroll
    for (int i = 0; i < 32; i++) {
        float qo[2], ko[2];
#pragma unroll
        for (int e = 0; e < 2; e++) {
            const int d = 2 * i + e;
            float cc, sn;
            __sincosf(q[d], &sn, &cc);
            const float rq = (d < 32) ? -q[2 * d + 1] : q[2 * d - 64];
            const float rk = (d < 32) ? -k[2 * d + 1] : k[2 * d - 64];
            qo[e] = q[d] * cc + rq * sn;
            ko[e] = k[d] * cc + rk * sn;
        }
        qh32[i] = packbf(qo[0], qo[1]);
        ql32[i] = packbf(qo[0] - __bfloat162float(__float2bfloat16(qo[0])),
                         qo[1] - __bfloat162float(__float2bfloat16(qo[1])));
        kh32[i] = packbf(ko[0], ko[1]);
        kl32[i] = packbf(ko[0] - __bfloat162float(__float2bfloat16(ko[0])),
                         ko[1] - __bfloat162float(__float2bfloat16(ko[1])));
    }
}

// ---------------------------------------------------------------------------
// Tensor-core flash attention, 128-key chunks (verified R14).
// QK^T: bf16x3. PV: fp16 P x single-fp16 V. KV chunk = 3 tiles.
// ---------------------------------------------------------------------------
#define SKB 144
#define KTILE (128 * SKB)            // 18432
#define KVBUF (3 * KTILE)            // khi, klo, vhi
#define DSMEM_A (2 * KTILE + 2 * KVBUF)  // 147456 (1 CTA/SM)

__global__ __launch_bounds__(256, 1) void attn_mma() {
    extern __shared__ char dsm[];
    const uint32_t sbase = smem_u32(dsm);
    const uint32_t kvbase = sbase + 2 * KTILE;

    const int tid  = threadIdx.x;
    const int lane = tid & 31;
    const int wid  = tid >> 5;
    const int wm   = wid * 16;
    const int bh   = blockIdx.y;
    const int q0   = blockIdx.x * 128;
    const int nc   = blockIdx.x + 1;

    {
        const __nv_bfloat16* qs[2] = {g_qhi, g_qlo};
#pragma unroll
        for (int it = 0; it < 8; it++) {
            const int idx = tid + it * 256;
            const int half = idx >> 10;
            const int rem = idx & 1023;
            const int row = rem >> 3;
            const int seg = rem & 7;
            cp16(sbase + (uint32_t)half * KTILE + (uint32_t)row * SKB + seg * 16,
                 qs[half] + ((size_t)(bh * T_LEN + q0 + row) * D_HEAD + seg * 8));
        }
        cp_commit();
    }

    const __nv_bfloat16* kvsrc[3] = {g_khi, g_klo, g_vhi};
    auto issue_kv = [&](int j0, int buf) {
#pragma unroll
        for (int it = 0; it < 12; it++) {
            const int idx = tid + it * 256;
            const int sub = idx >> 10;
            const int rem = idx & 1023;
            const int row = rem >> 3;
            const int seg = rem & 7;
            cp16(kvbase + (uint32_t)buf * KVBUF + (uint32_t)sub * KTILE
                     + (uint32_t)row * SKB + seg * 16,
                 kvsrc[sub] + ((size_t)(bh * T_LEN + j0 + row) * D_HEAD + seg * 8));
        }
        cp_commit();
    };

    issue_kv(0, 0);

    float o[8][4];
#pragma unroll
    for (int ni = 0; ni < 8; ni++)
#pragma unroll
        for (int e = 0; e < 4; e++) o[ni][e] = 0.f;
    float m0 = -1e30f, m1 = -1e30f, l0 = 0.f, l1 = 0.f;
    uint32_t qh[4][4], ql[4][4];

    const int g  = lane >> 2;
    const int tg = lane & 3;
    const int brow = lane & 7;
    const int bsel = ((lane >> 3) & 1) * 8;

    for (int c = 0; c < nc; c++) {
        const int j0 = c * 128;
        if (c + 1 < nc) { issue_kv((c + 1) * 128, (c + 1) & 1); cp_wait1(); }
        else            { cp_wait0(); }
        __syncthreads();

        if (c == 0) {
            const int arow = lane & 15;
            const int acol = (lane >> 4) << 3;
#pragma unroll
            for (int k16 = 0; k16 < 4; k16++) {
                const uint32_t ad = sbase + (uint32_t)(wm + arow) * SKB
                                  + (uint32_t)(k16 * 16 + acol) * 2;
                ldmat4(qh[k16], ad);
                ldmat4(ql[k16], ad + KTILE);
            }
        }

        const uint32_t kb = kvbase + (uint32_t)(c & 1) * KVBUF;

        float s[16][4];
#pragma unroll
        for (int ni = 0; ni < 16; ni++) {
#pragma unroll
            for (int e = 0; e < 4; e++) s[ni][e] = 0.f;
#pragma unroll
            for (int k16 = 0; k16 < 4; k16++) {
                const uint32_t bd = kb + (uint32_t)(ni * 8 + brow) * SKB
                                  + (uint32_t)(k16 * 16 + bsel) * 2;
                uint32_t kh[2], kl[2];
                ldmat2(kh, bd);
                ldmat2(kl, bd + KTILE);
                mma16816(s[ni], qh[k16], kh);
                mma16816(s[ni], qh[k16], kl);
                mma16816(s[ni], ql[k16], kh);
            }
        }

        if (c == nc - 1) {
            const int r0 = q0 + wm + g;
#pragma unroll
            for (int ni = 0; ni < 16; ni++) {
                const int cbase = j0 + ni * 8 + 2 * tg;
#pragma unroll
                for (int e = 0; e < 4; e++) {
                    const int col = cbase + (e & 1);
                    const int row = (e < 2) ? r0 : r0 + 8;
                    if (col > row) s[ni][e] = -1e30f;
                }
            }
        }

        float tm0 = -1e30f, tm1 = -1e30f;
#pragma unroll
        for (int ni = 0; ni < 16; ni++) {
            tm0 = fmaxf(tm0, fmaxf(s[ni][0], s[ni][1]));
            tm1 = fmaxf(tm1, fmaxf(s[ni][2], s[ni][3]));
        }
        tm0 = qmax(tm0); tm1 = qmax(tm1);
        const float mn0 = fmaxf(m0, tm0);
        const float mn1 = fmaxf(m1, tm1);
        const float corr0 = __expf(m0 - mn0);
        const float corr1 = __expf(m1 - mn1);
        m0 = mn0; m1 = mn1;

        float ps0 = 0.f, ps1 = 0.f;
#pragma unroll
        for (int ni = 0; ni < 16; ni++) {
            s[ni][0] = __expf(s[ni][0] - m0);
            s[ni][1] = __expf(s[ni][1] - m0);
            s[ni][2] = __expf(s[ni][2] - m1);
            s[ni][3] = __expf(s[ni][3] - m1);
            ps0 += s[ni][0] + s[ni][1];
            ps1 += s[ni][2] + s[ni][3];
        }
        ps0 = qsum(ps0); ps1 = qsum(ps1);
        l0 = l0 * corr0 + ps0;
        l1 = l1 * corr1 + ps1;
#pragma unroll
        for (int ni = 0; ni < 8; ni++) {
            o[ni][0] *= corr0; o[ni][1] *= corr0;
            o[ni][2] *= corr1; o[ni][3] *= corr1;
        }

#pragma unroll
        for (int kj = 0; kj < 8; kj++) {
            uint32_t Ah[4];
#pragma unroll
            for (int half = 0; half < 2; half++) {
                const int sn = 2 * kj + half;
                Ah[2 * half + 0] = packh(s[sn][0], s[sn][1]);
                Ah[2 * half + 1] = packh(s[sn][2], s[sn][3]);
            }
            const int vrow = kj * 16 + bsel + brow;
#pragma unroll
            for (int ni = 0; ni < 8; ni++) {
                const uint32_t vd = kb + 2 * KTILE + (uint32_t)vrow * SKB + ni * 16;
                uint32_t vh[2];
                ldmat2t(vh, vd);
                mma16816h(o[ni], Ah, vh);
            }
        }
        __syncthreads();
    }

    const float inv0 = 1.f / l0;
    const float inv1 = 1.f / l1;
    const int b = bh >> 4;
    const int h = bh & 15;
    const int r0 = q0 + wm + g;
#pragma unroll
    for (int ni = 0; ni < 8; ni++) {
        const int d = ni * 8 + 2 * tg;
#pragma unroll
        for (int rr = 0; rr < 2; rr++) {
            const int row = r0 + rr * 8;
            const float y0 = o[ni][2 * rr + 0] * (rr ? inv1 : inv0);
            const float y1 = o[ni][2 * rr + 1] * (rr ? inv1 : inv0);
            const size_t off = (size_t)(b * T_LEN + row) * C_DIM + h * D_HEAD + d;
            *(uint32_t*)(g_yhi + off) = packh(y0, y1);
        }
    }
}

// ---------------------------------------------------------------------------
extern "C" void kernel_launch(void* const* d_in, const int* in_sizes, int n_in,
                              void* d_out, int out_size) {
    const float* x  = (const float*)d_in[0];   // (8,1024,1024)
    const float* Wa = (const float*)d_in[1];   // (3072,1024)
    const float* Wp = (const float*)d_in[2];   // (1024,1024)
    float* out = (float*)d_out;                // (8,1024,1024)

    cudaFuncSetAttribute(gemm_qkv,  cudaFuncAttributeMaxDynamicSharedMemorySize, DSMEM_Q);
    cudaFuncSetAttribute(gemm_proj, cudaFuncAttributeMaxDynamicSharedMemorySize, DSMEM_P);
    cudaFuncSetAttribute(attn_mma,  cudaFuncAttributeMaxDynamicSharedMemorySize, DSMEM_A);

    __nv_bfloat16 *xhi, *xlo, *wahi, *walo, *wph, *yhi;
    cudaGetSymbolAddress((void**)&xhi,  g_xhi);
    cudaGetSymbolAddress((void**)&xlo,  g_xlo);
    cudaGetSymbolAddress((void**)&wahi, g_wahi);
    cudaGetSymbolAddress((void**)&walo, g_walo);
    cudaGetSymbolAddress((void**)&wph,  g_wph);
    cudaGetSymbolAddress((void**)&yhi,  g_yhi);

    // 1) input conversions
    hsplit_kernel<<<(M_ROWS * K_DIM / 4) / 256, 256>>>(x,  xhi,  xlo,  M_ROWS * K_DIM / 4);
    hsplit_kernel<<<(3 * C_DIM * K_DIM / 4) / 256, 256>>>(Wa, wahi, walo, 3 * C_DIM * K_DIM / 4);
    half_kernel<<<(C_DIM * K_DIM / 4) / 256, 256>>>(Wp, wph, C_DIM * K_DIM / 4);

    // 2) QKV GEMM (fp16; 256x128 tile, 3-stage pipeline)
    gemm_qkv<<<dim3(3072 / 128, M_ROWS / 256), 256, DSMEM_Q>>>(xhi, xlo, wahi, walo);

    // 3) Rotary
    rotary_kernel<<<(BH * T_LEN) / 256, 256>>>();

    // 4) Flash attention (QK bf16x3, PV fp16 1-term)
    attn_mma<<<dim3(T_LEN / 128, BH), 256, DSMEM_A>>>();

    // 5) Projection GEMM (fp16 1-term)
    gemm_proj<<<dim3(1024 / 128, M_ROWS / 128), 256, DSMEM_P>>>(yhi, wph, out);
}

// round 16
// speedup vs baseline: 1.0972x; 1.0972x over previous
#include <cuda_runtime.h>
#include <cuda_bf16.h>
#include <cuda_fp16.h>
#include <math.h>
#include <stdint.h>

// Problem constants
#define B_SZ   8
#define T_LEN  1024
#define C_DIM  1024
#define H_NUM  16
#define D_HEAD 64
#define BH     (B_SZ * H_NUM)        // 128
#define M_ROWS (B_SZ * T_LEN)        // 8192
#define K_DIM  1024

// fp32 scratch (pre-rotary q/k only)
__device__ float g_q[BH * T_LEN * D_HEAD];
__device__ float g_k[BH * T_LEN * D_HEAD];

// 16-bit buffers (payload dtype noted; arrays typed bf16 for storage only)
__device__ __nv_bfloat16 g_xhi[M_ROWS * K_DIM];         // fp16 payload
__device__ __nv_bfloat16 g_xlo[M_ROWS * K_DIM];         // fp16 payload
__device__ __nv_bfloat16 g_wahi[3 * C_DIM * K_DIM];     // fp16 payload
__device__ __nv_bfloat16 g_walo[3 * C_DIM * K_DIM];     // fp16 payload
__device__ __nv_bfloat16 g_wph[C_DIM * K_DIM];          // fp16 payload
__device__ __nv_bfloat16 g_qhi[BH * T_LEN * D_HEAD];    // bf16
__device__ __nv_bfloat16 g_qlo[BH * T_LEN * D_HEAD];    // bf16
__device__ __nv_bfloat16 g_khi[BH * T_LEN * D_HEAD];    // bf16
__device__ __nv_bfloat16 g_klo[BH * T_LEN * D_HEAD];    // bf16
__device__ __nv_bfloat16 g_vhi[BH * T_LEN * D_HEAD];    // fp16 payload (single)
__device__ __nv_bfloat16 g_yhi[M_ROWS * C_DIM];         // fp16 payload (single)

// ---------------------------------------------------------------------------
// helpers
// ---------------------------------------------------------------------------
__device__ __forceinline__ uint32_t smem_u32(const void* p) {
    uint32_t a;
    asm("{ .reg .u64 t; cvta.to.shared.u64 t, %1; cvt.u32.u64 %0, t; }"
        : "=r"(a) : "l"(p));
    return a;
}
__device__ __forceinline__ void cp16(uint32_t dst, const void* src) {
    asm volatile("cp.async.cg.shared.global [%0], [%1], 16;" :: "r"(dst), "l"(src));
}
__device__ __forceinline__ void cp_commit() {
    asm volatile("cp.async.commit_group;" ::: "memory");
}
__device__ __forceinline__ void cp_wait1() {
    asm volatile("cp.async.wait_group 1;" ::: "memory");
}
__device__ __forceinline__ void cp_wait0() {
    asm volatile("cp.async.wait_group 0;" ::: "memory");
}
__device__ __forceinline__ void ldmat4(uint32_t* r, uint32_t addr) {
    asm volatile("ldmatrix.sync.aligned.m8n8.x4.shared.b16 {%0,%1,%2,%3}, [%4];"
                 : "=r"(r[0]), "=r"(r[1]), "=r"(r[2]), "=r"(r[3]) : "r"(addr));
}
__device__ __forceinline__ void ldmat2(uint32_t* r, uint32_t addr) {
    asm volatile("ldmatrix.sync.aligned.m8n8.x2.shared.b16 {%0,%1}, [%2];"
                 : "=r"(r[0]), "=r"(r[1]) : "r"(addr));
}
__device__ __forceinline__ void ldmat2t(uint32_t* r, uint32_t addr) {
    asm volatile("ldmatrix.sync.aligned.m8n8.x2.trans.shared.b16 {%0,%1}, [%2];"
                 : "=r"(r[0]), "=r"(r[1]) : "r"(addr));
}
// bf16 MMA (fp32 accum)
__device__ __forceinline__ void mma16816(float* c, const uint32_t* a, const uint32_t* b) {
    asm volatile(
        "mma.sync.aligned.m16n8k16.row.col.f32.bf16.bf16.f32 "
        "{%0,%1,%2,%3}, {%4,%5,%6,%7}, {%8,%9}, {%0,%1,%2,%3};"
        : "+f"(c[0]), "+f"(c[1]), "+f"(c[2]), "+f"(c[3])
        : "r"(a[0]), "r"(a[1]), "r"(a[2]), "r"(a[3]), "r"(b[0]), "r"(b[1]));
}
// fp16 MMA (fp32 accum)
__device__ __forceinline__ void mma16816h(float* c, const uint32_t* a, const uint32_t* b) {
    asm volatile(
        "mma.sync.aligned.m16n8k16.row.col.f32.f16.f16.f32 "
        "{%0,%1,%2,%3}, {%4,%5,%6,%7}, {%8,%9}, {%0,%1,%2,%3};"
        : "+f"(c[0]), "+f"(c[1]), "+f"(c[2]), "+f"(c[3])
        : "r"(a[0]), "r"(a[1]), "r"(a[2]), "r"(a[3]), "r"(b[0]), "r"(b[1]));
}
__device__ __forceinline__ uint32_t packbf(float a, float b) {
    uint32_t r;
    asm("cvt.rn.bf16x2.f32 %0, %1, %2;" : "=r"(r) : "f"(b), "f"(a));
    return r;
}
__device__ __forceinline__ uint32_t packh(float a, float b) {
    uint32_t r;
    asm("cvt.rn.f16x2.f32 %0, %1, %2;" : "=r"(r) : "f"(b), "f"(a));
    return r;
}
__device__ __forceinline__ float qmax(float x) {
    x = fmaxf(x, __shfl_xor_sync(0xffffffffu, x, 1));
    x = fmaxf(x, __shfl_xor_sync(0xffffffffu, x, 2));
    return x;
}
__device__ __forceinline__ float qsum(float x) {
    x += __shfl_xor_sync(0xffffffffu, x, 1);
    x += __shfl_xor_sync(0xffffffffu, x, 2);
    return x;
}

// ---------------------------------------------------------------------------
// fp32 -> (fp16 hi, fp16 lo) split, 8 elems/thread
// ---------------------------------------------------------------------------
__global__ __launch_bounds__(256) void hsplit_kernel(const float* __restrict__ src,
                                                     __nv_bfloat16* __restrict__ hi,
                                                     __nv_bfloat16* __restrict__ lo,
                                                     int n8) {
    int i = blockIdx.x * blockDim.x + threadIdx.x;
    if (i >= n8) return;
    float4 x0 = ((const float4*)src)[2 * i + 0];
    float4 x1 = ((const float4*)src)[2 * i + 1];
    float xs[8] = {x0.x, x0.y, x0.z, x0.w, x1.x, x1.y, x1.z, x1.w};
    uint4 ho, lv;
    uint32_t* hp = &ho.x;
    uint32_t* lp = &lv.x;
#pragma unroll
    for (int p = 0; p < 4; p++) {
        const float a = xs[2 * p], b = xs[2 * p + 1];
        hp[p] = packh(a, b);
        const float ha = __half2float(__float2half(a));
        const float hb = __half2float(__float2half(b));
        lp[p] = packh(a - ha, b - hb);
    }
    ((uint4*)hi)[i] = ho;
    ((uint4*)lo)[i] = lv;
}

// fp32 -> fp16 (single) convert, 8 elems/thread, for Wp
__global__ __launch_bounds__(256) void half_kernel(const float* __restrict__ src,
                                                   __nv_bfloat16* __restrict__ dst,
                                                   int n8) {
    int i = blockIdx.x * blockDim.x + threadIdx.x;
    if (i >= n8) return;
    float4 x0 = ((const float4*)src)[2 * i + 0];
    float4 x1 = ((const float4*)src)[2 * i + 1];
    uint4 out;
    out.x = packh(x0.x, x0.y);
    out.y = packh(x0.z, x0.w);
    out.z = packh(x1.x, x1.y);
    out.w = packh(x1.z, x1.w);
    ((uint4*)dst)[i] = out;
}

// ---------------------------------------------------------------------------
// QKV GEMM (fp16): BK=32, 2 CTAs/SM (exact R14-verified kernel).
// q,k columns: 3 terms xh*Wh + xl*Wh + xh*Wl; v columns: 2 terms (xh+xl)*Wh.
// Epilogue: q,k fp32 head-layout; v -> single fp16 head-layout.
// ---------------------------------------------------------------------------
#define GSKE 40
#define GSKB (GSKE * 2)              // 80 bytes/row
#define GTILE (128 * GSKB)           // 10240
#define DSMEM (2 * 4 * GTILE)        // 81920

__global__ __launch_bounds__(256, 2) void gemm_qkv(
    const __nv_bfloat16* __restrict__ Ahi, const __nv_bfloat16* __restrict__ Alo,
    const __nv_bfloat16* __restrict__ Bhi, const __nv_bfloat16* __restrict__ Blo) {
    extern __shared__ char dsm[];
    const uint32_t sbase = smem_u32(dsm);

    const int tid  = threadIdx.x;
    const int lane = tid & 31;
    const int wid  = tid >> 5;
    const int wm   = (wid & 1) * 64;
    const int wn   = (wid >> 1) * 32;
    const int bn   = blockIdx.x * 128;
    const int bm   = blockIdx.y * 128;
    const bool qk  = (bn < 2048);

    float c[4][4][4];
#pragma unroll
    for (int mi = 0; mi < 4; mi++)
#pragma unroll
        for (int ni = 0; ni < 4; ni++)
#pragma unroll
            for (int e = 0; e < 4; e++) c[mi][ni][e] = 0.f;

    const __nv_bfloat16* srcs[4] = {Ahi, Alo, Bhi, Blo};
    const int gbase[2] = {bm, bn};

    auto issue = [&](int ch, int buf) {
        const int k0 = ch * 32;
#pragma unroll
        for (int t = 0; t < 4; t++) {
            if (t == 3 && !qk) continue;
            const __nv_bfloat16* src = srcs[t];
            const int gb = gbase[t >> 1];
            const uint32_t dbase = sbase + (uint32_t)(buf * 4 + t) * GTILE;
#pragma unroll
            for (int it = 0; it < 2; it++) {
                const int idx = tid + it * 256;
                const int row = idx >> 2;
                const int seg = idx & 3;
                cp16(dbase + (uint32_t)row * GSKB + seg * 16,
                     src + (size_t)(gb + row) * K_DIM + k0 + seg * 8);
            }
        }
        cp_commit();
    };

    issue(0, 0);

    const int arow = lane & 15;
    const int acol = (lane >> 4) << 3;
    const int brow = lane & 7;
    const int bcol = ((lane >> 3) & 1) << 3;

    for (int ch = 0; ch < 32; ch++) {
        cp_wait0();
        __syncthreads();
        if (ch < 31) issue(ch + 1, (ch + 1) & 1);

        const uint32_t abase = sbase + (uint32_t)((ch & 1) * 4 + 0) * GTILE;
        const uint32_t bbase = sbase + (uint32_t)((ch & 1) * 4 + 2) * GTILE;

#pragma unroll
        for (int k16 = 0; k16 < 2; k16++) {
            uint32_t bh[4][2], bl[4][2];
#pragma unroll
            for (int ni = 0; ni < 4; ni++) {
                const uint32_t bd = bbase + (uint32_t)(wn + ni * 8 + brow) * GSKB
                                  + (uint32_t)(k16 * 16 + bcol) * 2;
                ldmat2(bh[ni], bd);
                if (qk) ldmat2(bl[ni], bd + GTILE);
            }
#pragma unroll
            for (int mi = 0; mi < 4; mi++) {
                uint32_t ah[4], al[4];
                const uint32_t ad = abase + (uint32_t)(wm + mi * 16 + arow) * GSKB
                                  + (uint32_t)(k16 * 16 + acol) * 2;
                ldmat4(ah, ad);
                ldmat4(al, ad + GTILE);
#pragma unroll
                for (int ni = 0; ni < 4; ni++) {
                    mma16816h(c[mi][ni], ah, bh[ni]);
                    mma16816h(c[mi][ni], al, bh[ni]);
                    if (qk) mma16816h(c[mi][ni], ah, bl[ni]);
                }
            }
        }
    }

    const int g  = lane >> 2;
    const int tg = lane & 3;
#pragma unroll
    for (int mi = 0; mi < 4; mi++) {
#pragma unroll
        for (int ni = 0; ni < 4; ni++) {
            const int n = bn + wn + ni * 8 + 2 * tg;
            const int m0r = bm + wm + mi * 16 + g;
            const int part = n >> 10;
            const int cc = n & 1023;
            const int h = cc >> 6;
            const int d = cc & 63;
#pragma unroll
            for (int rr = 0; rr < 2; rr++) {
                const int m = m0r + rr * 8;
                const int b = m >> 10;
                const int t = m & 1023;
                const size_t off = ((size_t)(b * 16 + h) * T_LEN + t) * D_HEAD + d;
                float2 v = rr ? make_float2(c[mi][ni][2], c[mi][ni][3])
                              : make_float2(c[mi][ni][0], c[mi][ni][1]);
                if (part == 0)      *(float2*)(g_q + off) = v;
                else if (part == 1) *(float2*)(g_k + off) = v;
                else                *(uint32_t*)(g_vhi + off) = packh(v.x, v.y);
            }
        }
    }
}

// ---------------------------------------------------------------------------
// Projection GEMM (fp16, 1 term): out = y * Wp^T  (verified R14)
// ---------------------------------------------------------------------------
#define PBUF (2 * GTILE)             // 20480
#define DSMEM_P (2 * PBUF)           // 40960

__global__ __launch_bounds__(256, 2) void gemm_proj(
    const __nv_bfloat16* __restrict__ A, const __nv_bfloat16* __restrict__ B,
    float* __restrict__ Cout) {
    extern __shared__ char dsm[];
    const uint32_t sbase = smem_u32(dsm);

    const int tid  = threadIdx.x;
    const int lane = tid & 31;
    const int wid  = tid >> 5;
    const int wm   = (wid & 1) * 64;
    const int wn   = (wid >> 1) * 32;
    const int bn   = blockIdx.x * 128;
    const int bm   = blockIdx.y * 128;

    float c[4][4][4];
#pragma unroll
    for (int mi = 0; mi < 4; mi++)
#pragma unroll
        for (int ni = 0; ni < 4; ni++)
#pragma unroll
            for (int e = 0; e < 4; e++) c[mi][ni][e] = 0.f;

    const __nv_bfloat16* srcs[2] = {A, B};
    const int gbase[2] = {bm, bn};

    auto issue = [&](int ch, int buf) {
        const int k0 = ch * 32;
        const uint32_t bb = sbase + (uint32_t)buf * PBUF;
#pragma unroll
        for (int it = 0; it < 4; it++) {
            const int idx = tid + it * 256;
            const int t = idx >> 9;
            const int rem = idx & 511;
            const int row = rem >> 2;
            const int seg = rem & 3;
            cp16(bb + (uint32_t)t * GTILE + (uint32_t)row * GSKB + seg * 16,
                 srcs[t] + (size_t)(gbase[t] + row) * K_DIM + k0 + seg * 8);
        }
        cp_commit();
    };

    issue(0, 0);

    const int arow = lane & 15;
    const int acol = (lane >> 4) << 3;
    const int brow = lane & 7;
    const int bcol = ((lane >> 3) & 1) << 3;

    for (int ch = 0; ch < 32; ch++) {
        cp_wait0();
        __syncthreads();
        if (ch < 31) issue(ch + 1, (ch + 1) & 1);

        const uint32_t bb = sbase + (uint32_t)(ch & 1) * PBUF;
        const uint32_t abase = bb;
        const uint32_t bbase = bb + GTILE;

#pragma unroll
        for (int k16 = 0; k16 < 2; k16++) {
            uint32_t bw[4][2];
#pragma unroll
            for (int ni = 0; ni < 4; ni++) {
                const uint32_t bd = bbase + (uint32_t)(wn + ni * 8 + brow) * GSKB
                                  + (uint32_t)(k16 * 16 + bcol) * 2;
                ldmat2(bw[ni], bd);
            }
#pragma unroll
            for (int mi = 0; mi < 4; mi++) {
                uint32_t ah[4];
                const uint32_t ad = abase + (uint32_t)(wm + mi * 16 + arow) * GSKB
                                  + (uint32_t)(k16 * 16 + acol) * 2;
                ldmat4(ah, ad);
#pragma unroll
                for (int ni = 0; ni < 4; ni++)
                    mma16816h(c[mi][ni], ah, bw[ni]);
            }
        }
    }

    const int g  = lane >> 2;
    const int tg = lane & 3;
#pragma unroll
    for (int mi = 0; mi < 4; mi++) {
#pragma unroll
        for (int ni = 0; ni < 4; ni++) {
            const int n = bn + wn + ni * 8 + 2 * tg;
            const int m0r = bm + wm + mi * 16 + g;
            *(float2*)(Cout + (size_t)m0r * C_DIM + n) =
                make_float2(c[mi][ni][0], c[mi][ni][1]);
            *(float2*)(Cout + (size_t)(m0r + 8) * C_DIM + n) =
                make_float2(c[mi][ni][2], c[mi][ni][3]);
        }
    }
}

// ---------------------------------------------------------------------------
// Rotary: fast __sincosf; outputs bf16 hi/lo of rotated q,k (verified)
// ---------------------------------------------------------------------------
__global__ __launch_bounds__(256) void rotary_kernel() {
    const int idx = blockIdx.x * blockDim.x + threadIdx.x;
    if (idx >= BH * T_LEN) return;
    const float* qp = g_q + (size_t)idx * D_HEAD;
    const float* kp = g_k + (size_t)idx * D_HEAD;

    float q[64], k[64];
#pragma unroll
    for (int i = 0; i < 16; i++) {
        ((float4*)q)[i] = ((const float4*)qp)[i];
        ((float4*)k)[i] = ((const float4*)kp)[i];
    }
    uint32_t* qh32 = (uint32_t*)g_qhi + (size_t)idx * 32;
    uint32_t* ql32 = (uint32_t*)g_qlo + (size_t)idx * 32;
    uint32_t* kh32 = (uint32_t*)g_khi + (size_t)idx * 32;
    uint32_t* kl32 = (uint32_t*)g_klo + (size_t)idx * 32;

#pragma unroll
    for (int i = 0; i < 32; i++) {
        float qo[2], ko[2];
#pragma unroll
        for (int e = 0; e < 2; e++) {
            const int d = 2 * i + e;
            float cc, sn;
            __sincosf(q[d], &sn, &cc);
            const float rq = (d < 32) ? -q[2 * d + 1] : q[2 * d - 64];
            const float rk = (d < 32) ? -k[2 * d + 1] : k[2 * d - 64];
            qo[e] = q[d] * cc + rq * sn;
            ko[e] = k[d] * cc + rk * sn;
        }
        qh32[i] = packbf(qo[0], qo[1]);
        ql32[i] = packbf(qo[0] - __bfloat162float(__float2bfloat16(qo[0])),
                         qo[1] - __bfloat162float(__float2bfloat16(qo[1])));
        kh32[i] = packbf(ko[0], ko[1]);
        kl32[i] = packbf(ko[0] - __bfloat162float(__float2bfloat16(ko[0])),
                         ko[1] - __bfloat162float(__float2bfloat16(ko[1])));
    }
}

// ---------------------------------------------------------------------------
// Tensor-core flash attention, 128-key chunks (R14 math; single-sync pipeline).
// QK^T: bf16x3. PV: fp16 P x single-fp16 V. KV chunk = 3 tiles.
// ---------------------------------------------------------------------------
#define SKB 144
#define KTILE (128 * SKB)            // 18432
#define KVBUF (3 * KTILE)            // khi, klo, vhi
#define DSMEM_A (2 * KTILE + 2 * KVBUF)  // 147456 (1 CTA/SM)

__global__ __launch_bounds__(256, 1) void attn_mma() {
    extern __shared__ char dsm[];
    const uint32_t sbase = smem_u32(dsm);
    const uint32_t kvbase = sbase + 2 * KTILE;

    const int tid  = threadIdx.x;
    const int lane = tid & 31;
    const int wid  = tid >> 5;
    const int wm   = wid * 16;
    const int bh   = blockIdx.y;
    const int q0   = blockIdx.x * 128;
    const int nc   = blockIdx.x + 1;

    {
        const __nv_bfloat16* qs[2] = {g_qhi, g_qlo};
#pragma unroll
        for (int it = 0; it < 8; it++) {
            const int idx = tid + it * 256;
            const int half = idx >> 10;
            const int rem = idx & 1023;
            const int row = rem >> 3;
            const int seg = rem & 7;
            cp16(sbase + (uint32_t)half * KTILE + (uint32_t)row * SKB + seg * 16,
                 qs[half] + ((size_t)(bh * T_LEN + q0 + row) * D_HEAD + seg * 8));
        }
        cp_commit();
    }

    const __nv_bfloat16* kvsrc[3] = {g_khi, g_klo, g_vhi};
    auto issue_kv = [&](int j0, int buf) {
#pragma unroll
        for (int it = 0; it < 12; it++) {
            const int idx = tid + it * 256;
            const int sub = idx >> 10;
            const int rem = idx & 1023;
            const int row = rem >> 3;
            const int seg = rem & 7;
            cp16(kvbase + (uint32_t)buf * KVBUF + (uint32_t)sub * KTILE
                     + (uint32_t)row * SKB + seg * 16,
                 kvsrc[sub] + ((size_t)(bh * T_LEN + j0 + row) * D_HEAD + seg * 8));
        }
        cp_commit();
    };

    issue_kv(0, 0);

    float o[8][4];
#pragma unroll
    for (int ni = 0; ni < 8; ni++)
#pragma unroll
        for (int e = 0; e < 4; e++) o[ni][e] = 0.f;
    float m0 = -1e30f, m1 = -1e30f, l0 = 0.f, l1 = 0.f;
    uint32_t qh[4][4], ql[4][4];

    const int g  = lane >> 2;
    const int tg = lane & 3;
    const int brow = lane & 7;
    const int bsel = ((lane >> 3) & 1) * 8;

    for (int c = 0; c < nc; c++) {
        const int j0 = c * 128;
        // single-sync pipeline: everything pending (chunk c, and Q on c==0) lands,
        // sync also retires all prior reads of the other buffer, then prefetch.
        cp_wait0();
        __syncthreads();
        if (c + 1 < nc) issue_kv((c + 1) * 128, (c + 1) & 1);

        if (c == 0) {
            const int arow = lane & 15;
            const int acol = (lane >> 4) << 3;
#pragma unroll
            for (int k16 = 0; k16 < 4; k16++) {
                const uint32_t ad = sbase + (uint32_t)(wm + arow) * SKB
                                  + (uint32_t)(k16 * 16 + acol) * 2;
                ldmat4(qh[k16], ad);
                ldmat4(ql[k16], ad + KTILE);
            }
        }

        const uint32_t kb = kvbase + (uint32_t)(c & 1) * KVBUF;

        float s[16][4];
#pragma unroll
        for (int ni = 0; ni < 16; ni++) {
#pragma unroll
            for (int e = 0; e < 4; e++) s[ni][e] = 0.f;
#pragma unroll
            for (int k16 = 0; k16 < 4; k16++) {
                const uint32_t bd = kb + (uint32_t)(ni * 8 + brow) * SKB
                                  + (uint32_t)(k16 * 16 + bsel) * 2;
                uint32_t kh[2], kl[2];
                ldmat2(kh, bd);
                ldmat2(kl, bd + KTILE);
                mma16816(s[ni], qh[k16], kh);
                mma16816(s[ni], qh[k16], kl);
                mma16816(s[ni], ql[k16], kh);
            }
        }

        if (c == nc - 1) {
            const int r0 = q0 + wm + g;
#pragma unroll
            for (int ni = 0; ni < 16; ni++) {
                const int cbase = j0 + ni * 8 + 2 * tg;
#pragma unroll
                for (int e = 0; e < 4; e++) {
                    const int col = cbase + (e & 1);
                    const int row = (e < 2) ? r0 : r0 + 8;
                    if (col > row) s[ni][e] = -1e30f;
                }
            }
        }

        float tm0 = -1e30f, tm1 = -1e30f;
#pragma unroll
        for (int ni = 0; ni < 16; ni++) {
            tm0 = fmaxf(tm0, fmaxf(s[ni][0], s[ni][1]));
            tm1 = fmaxf(tm1, fmaxf(s[ni][2], s[ni][3]));
        }
        tm0 = qmax(tm0); tm1 = qmax(tm1);
        const float mn0 = fmaxf(m0, tm0);
        const float mn1 = fmaxf(m1, tm1);
        const float corr0 = __expf(m0 - mn0);
        const float corr1 = __expf(m1 - mn1);
        m0 = mn0; m1 = mn1;

        float ps0 = 0.f, ps1 = 0.f;
#pragma unroll
        for (int ni = 0; ni < 16; ni++) {
            s[ni][0] = __expf(s[ni][0] - m0);
            s[ni][1] = __expf(s[ni][1] - m0);
            s[ni][2] = __expf(s[ni][2] - m1);
            s[ni][3] = __expf(s[ni][3] - m1);
            ps0 += s[ni][0] + s[ni][1];
            ps1 += s[ni][2] + s[ni][3];
        }
        ps0 = qsum(ps0); ps1 = qsum(ps1);
        l0 = l0 * corr0 + ps0;
        l1 = l1 * corr1 + ps1;
#pragma unroll
        for (int ni = 0; ni < 8; ni++) {
            o[ni][0] *= corr0; o[ni][1] *= corr0;
            o[ni][2] *= corr1; o[ni][3] *= corr1;
        }

#pragma unroll
        for (int kj = 0; kj < 8; kj++) {
            uint32_t Ah[4];
#pragma unroll
            for (int half = 0; half < 2; half++) {
                const int sn = 2 * kj + half;
                Ah[2 * half + 0] = packh(s[sn][0], s[sn][1]);
                Ah[2 * half + 1] = packh(s[sn][2], s[sn][3]);
            }
            const int vrow = kj * 16 + bsel + brow;
#pragma unroll
            for (int ni = 0; ni < 8; ni++) {
                const uint32_t vd = kb + 2 * KTILE + (uint32_t)vrow * SKB + ni * 16;
                uint32_t vh[2];
                ldmat2t(vh, vd);
                mma16816h(o[ni], Ah, vh);
            }
        }
    }

    const float inv0 = 1.f / l0;
    const float inv1 = 1.f / l1;
    const int b = bh >> 4;
    const int h = bh & 15;
    const int r0 = q0 + wm + g;
#pragma unroll
    for (int ni = 0; ni < 8; ni++) {
        const int d = ni * 8 + 2 * tg;
#pragma unroll
        for (int rr = 0; rr < 2; rr++) {
            const int row = r0 + rr * 8;
            const float y0 = o[ni][2 * rr + 0] * (rr ? inv1 : inv0);
            const float y1 = o[ni][2 * rr + 1] * (rr ? inv1 : inv0);
            const size_t off = (size_t)(b * T_LEN + row) * C_DIM + h * D_HEAD + d;
            *(uint32_t*)(g_yhi + off) = packh(y0, y1);
        }
    }
}

// ---------------------------------------------------------------------------
extern "C" void kernel_launch(void* const* d_in, const int* in_sizes, int n_in,
                              void* d_out, int out_size) {
    const float* x  = (const float*)d_in[0];   // (8,1024,1024)
    const float* Wa = (const float*)d_in[1];   // (3072,1024)
    const float* Wp = (const float*)d_in[2];   // (1024,1024)
    float* out = (float*)d_out;                // (8,1024,1024)

    cudaFuncSetAttribute(gemm_qkv,  cudaFuncAttributeMaxDynamicSharedMemorySize, DSMEM);
    cudaFuncSetAttribute(gemm_proj, cudaFuncAttributeMaxDynamicSharedMemorySize, DSMEM_P);
    cudaFuncSetAttribute(attn_mma,  cudaFuncAttributeMaxDynamicSharedMemorySize, DSMEM_A);

    __nv_bfloat16 *xhi, *xlo, *wahi, *walo, *wph, *yhi;
    cudaGetSymbolAddress((void**)&xhi,  g_xhi);
    cudaGetSymbolAddress((void**)&xlo,  g_xlo);
    cudaGetSymbolAddress((void**)&wahi, g_wahi);
    cudaGetSymbolAddress((void**)&walo, g_walo);
    cudaGetSymbolAddress((void**)&wph,  g_wph);
    cudaGetSymbolAddress((void**)&yhi,  g_yhi);

    // 1) input conversions (8 elems/thread)
    hsplit_kernel<<<(M_ROWS * K_DIM / 8) / 256, 256>>>(x,  xhi,  xlo,  M_ROWS * K_DIM / 8);
    hsplit_kernel<<<(3 * C_DIM * K_DIM / 8) / 256, 256>>>(Wa, wahi, walo, 3 * C_DIM * K_DIM / 8);
    half_kernel<<<(C_DIM * K_DIM / 8) / 256, 256>>>(Wp, wph, C_DIM * K_DIM / 8);

    // 2) QKV GEMM (fp16; 3-term q,k / 2-term v)
    gemm_qkv<<<dim3(3072 / 128, M_ROWS / 128), 256, DSMEM>>>(xhi, xlo, wahi, walo);

    // 3) Rotary
    rotary_kernel<<<(BH * T_LEN) / 256, 256>>>();

    // 4) Flash attention (QK bf16x3, PV fp16 1-term)
    attn_mma<<<dim3(T_LEN / 128, BH), 256, DSMEM_A>>>();

    // 5) Projection GEMM (fp16 1-term)
    gemm_proj<<<dim3(1024 / 128, M_ROWS / 128), 256, DSMEM_P>>>(yhi, wph, out);
}